// round 6
// baseline (speedup 1.0000x reference)
#include <cuda_runtime.h>
#include <math.h>

#define DDIM 2048
#define EDIM 64
#define T_TILE 64
#define DTILE 32
#define NT (DDIM / DTILE)
#define XRP 70               // X row pitch in float2 (dup-pair) units; 70 -> 16B-aligned rows, 2-way-max store conflicts
#define AMB_TH 1e-3f

typedef unsigned long long ull;

__device__ __forceinline__ void fma2(ull &acc, ull a, ull b) {
    asm("fma.rn.f32x2 %0, %1, %2, %0;" : "+l"(acc) : "l"(a), "l"(b));
}
__device__ __forceinline__ float2 unpack2(ull v) {
    float lo, hi;
    asm("mov.b64 {%0,%1}, %2;" : "=f"(lo), "=f"(hi) : "l"(v));
    return make_float2(lo, hi);
}
__device__ __forceinline__ void cpasync16(float* smem_dst, const float* gsrc) {
    unsigned int d = (unsigned int)__cvta_generic_to_shared(smem_dst);
    asm volatile("cp.async.cg.shared.global [%0], [%1], 16;" :: "r"(d), "l"(gsrc));
}
#define CP_COMMIT() asm volatile("cp.async.commit_group;")
#define CP_WAIT0()  asm volatile("cp.async.wait_group 0;")

// dynamic smem: [2][DTILE][XRP] float2 X (dup pairs)  |  [2][2][DTILE][64] float W
// the noisy-logits epilogue buffer overlays the W region (compute done by then)
#define XBUF_F2   (2 * DTILE * XRP)          // float2 elements total
#define WBUF_F    (2 * 2 * DTILE * 64)       // floats total
#define DSM_BYTES (XBUF_F2 * 8 + WBUF_F * 4) // 35840 + 32768 = 68608

struct StaticSmem {
    float br[EDIM], bn[EDIM];
    float p1[T_TILE], p2[T_TILE];
    int   i1[T_TILE], i2[T_TILE];
    int   atok[T_TILE];
    int4  acand[T_TILE];
    int   na;
    double dot[8];
};

__global__ __launch_bounds__(128, 3) void router_kernel(
    const float* __restrict__ X,
    const float* __restrict__ Wr,
    const float* __restrict__ br,
    const float* __restrict__ Wn,
    const float* __restrict__ bn,
    const float* __restrict__ noise,
    float* __restrict__ out_probs,
    float* __restrict__ out_idx,
    int write_idx)
{
    extern __shared__ float dsm[];
    float2* xbuf = reinterpret_cast<float2*>(dsm);   // [2][DTILE][XRP]
    float*  wbuf = dsm + XBUF_F2 * 2;                // [2][2][DTILE][64]
    float*  nl   = wbuf;                             // overlay: [T_TILE][68]
    __shared__ StaticSmem ss;

    const int tid  = threadIdx.x;
    const int ecol = tid & 15;   // experts ecol*4 .. ecol*4+3 (2 packed pairs)
    const int trow = tid >> 4;   // tokens trow*8 .. trow*8+7
    const int lane = tid & 31;
    const int wid  = tid >> 5;
    const int tokBase = blockIdx.x * T_TILE;

    if (tid < EDIM) { ss.br[tid] = br[tid]; ss.bn[tid] = bn[tid]; }
    if (tid == 0) ss.na = 0;

    ull aR[8][2], aN[8][2];      // [token k][expert pair q]
#pragma unroll
    for (int k = 0; k < 8; k++) { aR[k][0]=0; aR[k][1]=0; aN[k][0]=0; aN[k][1]=0; }

    const int f0 = tid,       tok0 = f0 >> 3, dq0 = f0 & 7;
    const int f1 = tid + 128, tok1 = f1 >> 3, dq1 = f1 & 7;
    const int f2 = tid + 256, tok2 = f2 >> 3, dq2 = f2 & 7;
    const int f3 = tid + 384, tok3 = f3 >> 3, dq3 = f3 & 7;

    float4 rx[4];

    // ---- staging helpers ----
    auto ldgX = [&](int tile) {
        const float* xb = X + (size_t)tokBase * DDIM + tile * DTILE;
        rx[0] = *reinterpret_cast<const float4*>(xb + (size_t)tok0 * DDIM + dq0 * 4);
        rx[1] = *reinterpret_cast<const float4*>(xb + (size_t)tok1 * DDIM + dq1 * 4);
        rx[2] = *reinterpret_cast<const float4*>(xb + (size_t)tok2 * DDIM + dq2 * 4);
        rx[3] = *reinterpret_cast<const float4*>(xb + (size_t)tok3 * DDIM + dq3 * 4);
    };
    auto stsX = [&](int buf) {
        float2* xb = xbuf + buf * (DTILE * XRP);
        const int tk[4] = {tok0, tok1, tok2, tok3};
        const int dq[4] = {dq0, dq1, dq2, dq3};
#pragma unroll
        for (int j = 0; j < 4; j++) {
            float v[4] = {rx[j].x, rx[j].y, rx[j].z, rx[j].w};
#pragma unroll
            for (int c = 0; c < 4; c++)
                xb[(dq[j] * 4 + c) * XRP + tk[j]] = make_float2(v[c], v[c]);
        }
    };
    auto cpW = [&](int tile, int buf) {
        float* wb = wbuf + buf * (2 * DTILE * 64);
#pragma unroll
        for (int m = 0; m < 2; m++) {
            const float* Ws = m ? Wn : Wr;
            float* wd = wb + m * DTILE * 64;
#pragma unroll
            for (int j = 0; j < 4; j++) {
                int c = tid + j * 128;         // 512 16B chunks per matrix
                int dd = c >> 4, quad = c & 15;
                cpasync16(wd + dd * 64 + quad * 4,
                          Ws + (size_t)(tile * DTILE + dd) * EDIM + quad * 4);
            }
        }
        CP_COMMIT();
    };

    // ---- prologue ----
    ldgX(0);
    stsX(0);
    cpW(0, 0);
    ldgX(1);

    // ---- main loop: one barrier per tile, double-buffered ----
    for (int t = 0; t < NT; t++) {
        int b = t & 1;
        CP_WAIT0();
        __syncthreads();        // tile t staged & visible; buffers b^1 free
        if (t + 1 < NT) {
            stsX(b ^ 1);
            cpW(t + 1, b ^ 1);
        }
        if (t + 2 < NT) ldgX(t + 2);

        const ull*   xr = reinterpret_cast<const ull*>(xbuf + b * (DTILE * XRP)) + trow * 8;
        const float* wb = wbuf + b * (2 * DTILE * 64) + ecol * 4;
#pragma unroll
        for (int dd = 0; dd < DTILE; ++dd) {
            const ulonglong2* xv = reinterpret_cast<const ulonglong2*>(xr + dd * XRP);
            ulonglong2 x01 = xv[0], x23 = xv[1], x45 = xv[2], x67 = xv[3];
            ull xp[8] = {x01.x, x01.y, x23.x, x23.y, x45.x, x45.y, x67.x, x67.y};
            ulonglong2 wr2 = *reinterpret_cast<const ulonglong2*>(wb + dd * 64);
            ulonglong2 wn2 = *reinterpret_cast<const ulonglong2*>(wb + DTILE * 64 + dd * 64);
#pragma unroll
            for (int k = 0; k < 8; k++) {
                fma2(aR[k][0], xp[k], wr2.x);
                fma2(aR[k][1], xp[k], wr2.y);
                fma2(aN[k][0], xp[k], wn2.x);
                fma2(aN[k][1], xp[k], wn2.y);
            }
        }
    }
    __syncthreads();   // all compute done before nl overlays the W region

    // ---- epilogue: noisy logits -> smem ----
#pragma unroll
    for (int k = 0; k < 8; ++k) {
        int t = trow * 8 + k;
        float4 nz4 = *reinterpret_cast<const float4*>(
            noise + (size_t)(tokBase + t) * EDIM + ecol * 4);
        float nzv[4] = {nz4.x, nz4.y, nz4.z, nz4.w};
#pragma unroll
        for (int q = 0; q < 2; q++) {
            float2 rr = unpack2(aR[k][q]);
            float2 nn = unpack2(aN[k][q]);
#pragma unroll
            for (int h = 0; h < 2; h++) {
                int e = ecol * 4 + 2 * q + h;
                float lr = (h ? rr.y : rr.x) + ss.br[e];
                float ln = (h ? nn.y : nn.x) + ss.bn[e];
                // jax.nn.softplus(x) = max(x,0) + log1p(exp(-|x|))
                float sp = fmaxf(ln, 0.0f) + log1pf(expf(-fabsf(ln)));
                nl[t * 68 + e] = lr + nzv[2 * q + h] * sp;
            }
        }
    }
    __syncthreads();

    // ---- top-4 scan + 2-way softmax, one thread per token ----
    if (tid < T_TILE) {
        float v1 = -INFINITY, v2 = -INFINITY, v3 = -INFINITY, v4 = -INFINITY;
        int i1 = 0, i2 = 0, i3 = 0, i4 = 0;
        for (int e = 0; e < EDIM; e++) {
            float v = nl[tid * 68 + e];
            if (v > v1)      { v4=v3; i4=i3; v3=v2; i3=i2; v2=v1; i2=i1; v1=v; i1=e; }
            else if (v > v2) { v4=v3; i4=i3; v3=v2; i3=i2; v2=v;  i2=e; }
            else if (v > v3) { v4=v3; i4=i3; v3=v;  i3=e; }
            else if (v > v4) { v4=v;  i4=e; }
        }
        float ed = expf(v2 - v1);
        float s  = 1.0f + ed;
        ss.p1[tid] = 1.0f / s;
        ss.p2[tid] = ed / s;
        ss.i1[tid] = i1;
        ss.i2[tid] = i2;
        if (write_idx) {
            out_idx[(size_t)(tokBase + tid) * 2 + 0] = (float)i1;
            out_idx[(size_t)(tokBase + tid) * 2 + 1] = (float)i2;
        }
        if ((v1 - v2) < AMB_TH || (v2 - v3) < AMB_TH) {
            int slot = atomicAdd(&ss.na, 1);
            ss.atok[slot]  = tid;
            ss.acand[slot] = make_int4(i1, i2, i3, i4);
        }
    }
    __syncthreads();

    // ---- cooperative coalesced probs write ----
#pragma unroll
    for (int k = 0; k < 8; k++) {
        int f   = tid + k * 128;
        int tok = f >> 4;
        int q   = f & 15;
        int i1 = ss.i1[tok], i2 = ss.i2[tok];
        float p1 = ss.p1[tok], p2 = ss.p2[tok];
        float v[4] = {0.0f, 0.0f, 0.0f, 0.0f};
        int b = q * 4;
        if (i1 >= b && i1 < b + 4) v[i1 - b] = p1;
        if (i2 >= b && i2 < b + 4) v[i2 - b] = p2;
        *reinterpret_cast<float4*>(out_probs + (size_t)(tokBase + tok) * EDIM + b) =
            make_float4(v[0], v[1], v[2], v[3]);
    }
    __syncthreads();   // probs fully written before refine patches

    // ---- in-block fp64 arbitration for near-tie tokens (rare) ----
    int na = ss.na;
    for (int a = 0; a < na; a++) {
        int tok = tokBase + ss.atok[a];
        int4 cd = ss.acand[a];
        int cand[4] = {cd.x, cd.y, cd.z, cd.w};

        int c = cand[wid];
        const float* Xr = X + (size_t)tok * DDIM;
        double accR = 0.0, accN = 0.0;
        for (int d = lane; d < DDIM; d += 32) {
            double xv = (double)Xr[d];
            accR = fma(xv, (double)Wr[(size_t)d * EDIM + c], accR);
            accN = fma(xv, (double)Wn[(size_t)d * EDIM + c], accN);
        }
#pragma unroll
        for (int off = 16; off; off >>= 1) {
            accR += __shfl_down_sync(0xffffffffu, accR, off);
            accN += __shfl_down_sync(0xffffffffu, accN, off);
        }
        if (lane == 0) { ss.dot[wid] = accR; ss.dot[4 + wid] = accN; }
        __syncthreads();

        if (tid == 0) {
            double nv[4];
#pragma unroll
            for (int k = 0; k < 4; k++) {
                double lg = ss.dot[k]     + (double)br[cand[k]];
                double nv2 = ss.dot[4 + k] + (double)bn[cand[k]];
                double sp = fmax(nv2, 0.0) + log1p(exp(-fabs(nv2)));
                nv[k] = lg + (double)noise[(size_t)tok * EDIM + cand[k]] * sp;
            }
            int b1 = 0;
            for (int k = 1; k < 4; k++)
                if (nv[k] > nv[b1] || (nv[k] == nv[b1] && cand[k] < cand[b1])) b1 = k;
            int b2 = -1;
            for (int k = 0; k < 4; k++) {
                if (k == b1) continue;
                if (b2 < 0 || nv[k] > nv[b2] || (nv[k] == nv[b2] && cand[k] < cand[b2])) b2 = k;
            }
            double e = exp(nv[b2] - nv[b1]);
            double s = 1.0 + e;
            float p1 = (float)(1.0 / s);
            float p2 = (float)(e / s);
#pragma unroll
            for (int k = 0; k < 4; k++) {
                float pv = (k == b1) ? p1 : ((k == b2) ? p2 : 0.0f);
                out_probs[(size_t)tok * EDIM + cand[k]] = pv;
            }
            if (write_idx) {
                out_idx[(size_t)tok * 2 + 0] = (float)cand[b1];
                out_idx[(size_t)tok * 2 + 1] = (float)cand[b2];
            }
        }
        __syncthreads();
    }
}

extern "C" void kernel_launch(void* const* d_in, const int* in_sizes, int n_in,
                              void* d_out, int out_size) {
    const float* X     = (const float*)d_in[0];   // mh_output [B,S,D]
    const float* Wr    = (const float*)d_in[1];   // W_route   [D,E]
    const float* br    = (const float*)d_in[2];   // b_route   [E]
    const float* Wn    = (const float*)d_in[3];   // W_noise   [D,E]
    const float* bn    = (const float*)d_in[4];   // b_noise   [E]
    const float* noise = (const float*)d_in[5];   // noise     [B,S,E]

    int T = in_sizes[0] / DDIM;                   // 16384 tokens
    float* out       = (float*)d_out;
    float* out_probs = out;                       // [T, E]
    float* out_idx   = out + (size_t)T * EDIM;    // [T, 2] as floats (if present)
    int write_idx = (out_size >= T * EDIM + T * 2) ? 1 : 0;

    cudaFuncSetAttribute(router_kernel,
                         cudaFuncAttributeMaxDynamicSharedMemorySize, DSM_BYTES);
    router_kernel<<<T / T_TILE, 128, DSM_BYTES>>>(X, Wr, br, Wn, bn, noise,
                                                  out_probs, out_idx, write_idx);
}

// round 8
// speedup vs baseline: 1.1033x; 1.1033x over previous
#include <cuda_runtime.h>
#include <cuda_bf16.h>
#include <math.h>
#include <stdint.h>

#define DDIM 2048
#define EDIM 64
#define MTILE 128
#define KTILE 64
#define NKT (DDIM / KTILE)    // 32
#define AMB_TH 1e-3f

// Prepped W in B-fragment order:
// word P = ((((mat*2+split)*128 + kc)*32 + lane)*8 + nt)*2 + reg
// holds bf16 pair ( W[k0][col], W[k0+1][col] ),
//   col = nt*8 + lane/4,  k0 = kc*16 + (lane%4)*2 + 8*reg
__device__ __align__(16) uint32_t g_wb[2u * 2u * 128u * 32u * 8u * 2u];  // 1 MB

__device__ __forceinline__ uint32_t pack_bf16(__nv_bfloat16 a, __nv_bfloat16 b) {
    return (uint32_t)__bfloat16_as_ushort(a) | ((uint32_t)__bfloat16_as_ushort(b) << 16);
}

__global__ void prep_w(const float* __restrict__ Wr, const float* __restrict__ Wn) {
    int P = blockIdx.x * blockDim.x + threadIdx.x;      // 262144 words
    int reg = P & 1, nt = (P >> 1) & 7, lane = (P >> 4) & 31;
    int kc = (P >> 9) & 127, split = (P >> 16) & 1, mat = P >> 17;
    const float* W = mat ? Wn : Wr;
    int col = nt * 8 + (lane >> 2);
    int k0  = kc * 16 + (lane & 3) * 2 + 8 * reg;
    float w0 = W[(size_t)k0 * EDIM + col];
    float w1 = W[(size_t)(k0 + 1) * EDIM + col];
    __nv_bfloat16 b0, b1;
    if (split == 0) {
        b0 = __float2bfloat16_rn(w0);
        b1 = __float2bfloat16_rn(w1);
    } else {
        __nv_bfloat16 h0 = __float2bfloat16_rn(w0), h1 = __float2bfloat16_rn(w1);
        b0 = __float2bfloat16_rn(w0 - __bfloat162float(h0));
        b1 = __float2bfloat16_rn(w1 - __bfloat162float(h1));
    }
    g_wb[P] = pack_bf16(b0, b1);
}

__device__ __forceinline__ void mma16816(float* d,
                                         uint32_t a0, uint32_t a1, uint32_t a2, uint32_t a3,
                                         uint32_t b0, uint32_t b1) {
    asm volatile(
        "mma.sync.aligned.m16n8k16.row.col.f32.bf16.bf16.f32 "
        "{%0,%1,%2,%3}, {%4,%5,%6,%7}, {%8,%9}, {%0,%1,%2,%3};"
        : "+f"(d[0]), "+f"(d[1]), "+f"(d[2]), "+f"(d[3])
        : "r"(a0), "r"(a1), "r"(a2), "r"(a3), "r"(b0), "r"(b1));
}

struct SS {
    float br[EDIM], bn[EDIM];
    float p1[MTILE], p2[MTILE];
    int   i1[MTILE], i2[MTILE];
    int   atok[MTILE];
    int4  acand[MTILE];
    int   na;
    double dot[8];
};

// dynamic smem: X frag tiles [buf][split][4096 words] = 2*2*16KB = 64KB.
// A-frag slot S = ((kc*8 + tc)*32 + lane)*4 + reg:
//   tok = tc*16 + lane/4 + 8*(reg&1),  k = kc*16 + (lane%4)*2 + 8*(reg>>1)
#define DSMB 65536

__global__ __launch_bounds__(256, 1) void moe_kernel(
    const float* __restrict__ X,
    const float* __restrict__ br_g, const float* __restrict__ bn_g,
    const float* __restrict__ Wr, const float* __restrict__ Wn,
    const float* __restrict__ noise,
    float* __restrict__ out_probs, float* __restrict__ out_idx, int write_idx)
{
    extern __shared__ char ds[];
    __shared__ SS ss;

    const int tid = threadIdx.x, lane = tid & 31, w = tid >> 5;   // 8 warps
    const int tokBase = blockIdx.x * MTILE;

    if (tid < EDIM) { ss.br[tid] = br_g[tid]; ss.bn[tid] = bn_g[tid]; }
    if (tid == 0) ss.na = 0;

    float acc[2][8][4];
#pragma unroll
    for (int m = 0; m < 2; m++)
#pragma unroll
        for (int nt = 0; nt < 8; nt++)
#pragma unroll
            for (int q = 0; q < 4; q++) acc[m][nt][q] = 0.0f;

    float2 rx[16];
    auto ldgX = [&](int t) {
#pragma unroll
        for (int j = 0; j < 16; j++) {
            int S = tid + j * 256;
            int reg = S & 3, lf = (S >> 2) & 31, tc = (S >> 7) & 7, kc = S >> 10;
            int tok = tc * 16 + (lf >> 2) + 8 * (reg & 1);
            int kk  = kc * 16 + (lf & 3) * 2 + 8 * (reg >> 1);
            rx[j] = *reinterpret_cast<const float2*>(
                X + (size_t)(tokBase + tok) * DDIM + t * KTILE + kk);
        }
    };
    auto stsX = [&](int buf) {
#pragma unroll
        for (int j = 0; j < 16; j++) {
            int S = tid + j * 256;
            float2 v = rx[j];
            __nv_bfloat16 h0 = __float2bfloat16_rn(v.x), h1 = __float2bfloat16_rn(v.y);
            __nv_bfloat16 l0 = __float2bfloat16_rn(v.x - __bfloat162float(h0));
            __nv_bfloat16 l1 = __float2bfloat16_rn(v.y - __bfloat162float(h1));
            *reinterpret_cast<uint32_t*>(ds + buf * 32768 + S * 4) = pack_bf16(h0, h1);
            *reinterpret_cast<uint32_t*>(ds + buf * 32768 + 16384 + S * 4) = pack_bf16(l0, l1);
        }
    };

    ldgX(0);
    for (int t = 0; t < NKT; t++) {
        int buf = t & 1;
        stsX(buf);
        __syncthreads();          // one barrier/tile; double buffer covers WAR
        if (t + 1 < NKT) ldgX(t + 1);

#pragma unroll
        for (int kc = 0; kc < 4; kc++) {
            uint4 AH = *reinterpret_cast<const uint4*>(
                ds + buf * 32768 + ((kc * 8 + w) * 32 + lane) * 16);
            uint4 AL = *reinterpret_cast<const uint4*>(
                ds + buf * 32768 + 16384 + ((kc * 8 + w) * 32 + lane) * 16);
            int kcg = t * 4 + kc;
#pragma unroll
            for (int mat = 0; mat < 2; mat++) {
                const uint4* bhp = reinterpret_cast<const uint4*>(
                    g_wb + ((size_t)((mat * 2 + 0) * 128 + kcg) * 32 + lane) * 16);
                const uint4* blp = reinterpret_cast<const uint4*>(
                    g_wb + ((size_t)((mat * 2 + 1) * 128 + kcg) * 32 + lane) * 16);
                uint4 bh[4] = {bhp[0], bhp[1], bhp[2], bhp[3]};
                uint4 bl[4] = {blp[0], blp[1], blp[2], blp[3]};
                const uint32_t* bhw = reinterpret_cast<const uint32_t*>(bh);
                const uint32_t* blw = reinterpret_cast<const uint32_t*>(bl);
#pragma unroll
                for (int nt = 0; nt < 8; nt++) {
                    float* d = acc[mat][nt];
                    mma16816(d, AH.x, AH.y, AH.z, AH.w, bhw[nt*2], bhw[nt*2+1]); // hi*hi
                    mma16816(d, AL.x, AL.y, AL.z, AL.w, bhw[nt*2], bhw[nt*2+1]); // lo*hi
                    mma16816(d, AH.x, AH.y, AH.z, AH.w, blw[nt*2], blw[nt*2+1]); // hi*lo
                }
            }
        }
    }
    __syncthreads();   // compute done; X buffers reusable as nl

    // ---- epilogue: noisy logits -> smem nl[128][68] ----
    float* nl = reinterpret_cast<float*>(ds);
    {
        int r0 = w * 16 + (lane >> 2), r1 = r0 + 8;
        int c0 = (lane & 3) * 2;
#pragma unroll
        for (int nt = 0; nt < 8; nt++) {
            int e0 = nt * 8 + c0;
            float2 nzA = *reinterpret_cast<const float2*>(
                noise + (size_t)(tokBase + r0) * EDIM + e0);
            float2 nzB = *reinterpret_cast<const float2*>(
                noise + (size_t)(tokBase + r1) * EDIM + e0);
#pragma unroll
            for (int h = 0; h < 2; h++) {
                int e = e0 + h;
                // row r0 (acc idx 0/1), row r1 (acc idx 2/3)
                float lrA = acc[0][nt][h]     + ss.br[e];
                float lnA = acc[1][nt][h]     + ss.bn[e];
                float lrB = acc[0][nt][2 + h] + ss.br[e];
                float lnB = acc[1][nt][2 + h] + ss.bn[e];
                // jax.nn.softplus(x) = max(x,0) + log1p(exp(-|x|))
                float spA = fmaxf(lnA, 0.0f) + log1pf(expf(-fabsf(lnA)));
                float spB = fmaxf(lnB, 0.0f) + log1pf(expf(-fabsf(lnB)));
                nl[r0 * 68 + e] = lrA + (h ? nzA.y : nzA.x) * spA;
                nl[r1 * 68 + e] = lrB + (h ? nzB.y : nzB.x) * spB;
            }
        }
    }
    __syncthreads();

    // ---- top-4 scan + 2-way softmax, one thread per token ----
    if (tid < MTILE) {
        float v1 = -INFINITY, v2 = -INFINITY, v3 = -INFINITY, v4 = -INFINITY;
        int i1 = 0, i2 = 0, i3 = 0, i4 = 0;
        for (int e = 0; e < EDIM; e++) {
            float v = nl[tid * 68 + e];
            if (v > v1)      { v4=v3; i4=i3; v3=v2; i3=i2; v2=v1; i2=i1; v1=v; i1=e; }
            else if (v > v2) { v4=v3; i4=i3; v3=v2; i3=i2; v2=v;  i2=e; }
            else if (v > v3) { v4=v3; i4=i3; v3=v;  i3=e; }
            else if (v > v4) { v4=v;  i4=e; }
        }
        float ed = expf(v2 - v1);
        float s  = 1.0f + ed;
        ss.p1[tid] = 1.0f / s;
        ss.p2[tid] = ed / s;
        ss.i1[tid] = i1;
        ss.i2[tid] = i2;
        if (write_idx) {
            out_idx[(size_t)(tokBase + tid) * 2 + 0] = (float)i1;
            out_idx[(size_t)(tokBase + tid) * 2 + 1] = (float)i2;
        }
        if ((v1 - v2) < AMB_TH || (v2 - v3) < AMB_TH) {
            int slot = atomicAdd(&ss.na, 1);
            ss.atok[slot]  = tokBase + tid;
            ss.acand[slot] = make_int4(i1, i2, i3, i4);
        }
    }
    __syncthreads();

    // ---- cooperative coalesced probs write ----
#pragma unroll
    for (int k = 0; k < 8; k++) {
        int f   = tid + k * 256;
        int tok = f >> 4;
        int q   = f & 15;
        int i1 = ss.i1[tok], i2 = ss.i2[tok];
        float p1 = ss.p1[tok], p2 = ss.p2[tok];
        float v[4] = {0.0f, 0.0f, 0.0f, 0.0f};
        int b = q * 4;
        if (i1 >= b && i1 < b + 4) v[i1 - b] = p1;
        if (i2 >= b && i2 < b + 4) v[i2 - b] = p2;
        *reinterpret_cast<float4*>(out_probs + (size_t)(tokBase + tok) * EDIM + b) =
            make_float4(v[0], v[1], v[2], v[3]);
    }
    __syncthreads();

    // ---- fp64 arbitration for near-tie tokens (proven R5/R7 math) ----
    int na = ss.na;
    for (int a = 0; a < na; a++) {
        int tok = ss.atok[a];
        int4 cd = ss.acand[a];
        int cand[4] = {cd.x, cd.y, cd.z, cd.w};
        if (w < 4) {
            int c = cand[w];
            const float* Xr = X + (size_t)tok * DDIM;
            double accR = 0.0, accN = 0.0;
            for (int d = lane; d < DDIM; d += 32) {
                double xv = (double)Xr[d];
                accR = fma(xv, (double)Wr[(size_t)d * EDIM + c], accR);
                accN = fma(xv, (double)Wn[(size_t)d * EDIM + c], accN);
            }
#pragma unroll
            for (int off = 16; off; off >>= 1) {
                accR += __shfl_down_sync(0xffffffffu, accR, off);
                accN += __shfl_down_sync(0xffffffffu, accN, off);
            }
            if (lane == 0) { ss.dot[w] = accR; ss.dot[4 + w] = accN; }
        }
        __syncthreads();
        if (tid == 0) {
            double nv[4];
#pragma unroll
            for (int k = 0; k < 4; k++) {
                double lg = ss.dot[k]     + (double)ss.br[cand[k]];
                double nlg = ss.dot[4 + k] + (double)ss.bn[cand[k]];
                double sp = fmax(nlg, 0.0) + log1p(exp(-fabs(nlg)));
                nv[k] = lg + (double)noise[(size_t)tok * EDIM + cand[k]] * sp;
            }
            int b1 = 0;
            for (int k = 1; k < 4; k++)
                if (nv[k] > nv[b1] || (nv[k] == nv[b1] && cand[k] < cand[b1])) b1 = k;
            int b2 = -1;
            for (int k = 0; k < 4; k++) {
                if (k == b1) continue;
                if (b2 < 0 || nv[k] > nv[b2] || (nv[k] == nv[b2] && cand[k] < cand[b2])) b2 = k;
            }
            double e = exp(nv[b2] - nv[b1]);
            double s = 1.0 + e;
            float p1 = (float)(1.0 / s), p2 = (float)(e / s);
#pragma unroll
            for (int k = 0; k < 4; k++)
                out_probs[(size_t)tok * EDIM + cand[k]] =
                    (k == b1) ? p1 : ((k == b2) ? p2 : 0.0f);
            if (write_idx) {
                out_idx[(size_t)tok * 2 + 0] = (float)cand[b1];
                out_idx[(size_t)tok * 2 + 1] = (float)cand[b2];
            }
        }
        __syncthreads();
    }
}

extern "C" void kernel_launch(void* const* d_in, const int* in_sizes, int n_in,
                              void* d_out, int out_size) {
    const float* X     = (const float*)d_in[0];   // mh_output [B,S,D]
    const float* Wr    = (const float*)d_in[1];   // W_route   [D,E]
    const float* br    = (const float*)d_in[2];   // b_route   [E]
    const float* Wn    = (const float*)d_in[3];   // W_noise   [D,E]
    const float* bn    = (const float*)d_in[4];   // b_noise   [E]
    const float* noise = (const float*)d_in[5];   // noise     [B,S,E]

    int T = in_sizes[0] / DDIM;                   // 16384 tokens
    float* out       = (float*)d_out;
    float* out_probs = out;                       // [T, E]
    float* out_idx   = out + (size_t)T * EDIM;    // [T, 2] as floats (if present)
    int write_idx = (out_size >= T * EDIM + T * 2) ? 1 : 0;

    cudaFuncSetAttribute(moe_kernel,
                         cudaFuncAttributeMaxDynamicSharedMemorySize, DSMB);
    prep_w<<<1024, 256>>>(Wr, Wn);
    moe_kernel<<<T / MTILE, 256, DSMB>>>(X, br, bn, Wr, Wn, noise,
                                         out_probs, out_idx, write_idx);
}